// round 14
// baseline (speedup 1.0000x reference)
#include <cuda_runtime.h>
#include <cstdint>

// Problem constants
#define BB 8
#define TT 4096
#define DD 1024
#define DV2 (DD / 2)             // 512 float2 per row
#define LL 64                    // output timesteps per block
#define CC (TT / LL)             // 64 chunks
#define LANES (BB * DD)          // 8192 scalar lanes
#define VLANES2 (LANES / 2)      // 4096 float2 lanes
#define THR 256
#define NLB (VLANES2 / THR)      // 16 lane-blocks per chunk
#define GSTEP 4                  // timesteps per pipeline group
#define NGROUP (LL / GSTEP)      // 16 groups
#define NSTAGE 3                 // smem pipeline stages

__device__ float g_hfinal_scratch[LANES];

// Exact-ish sigmoid (used once, for lam)
__device__ __forceinline__ float fsig_exact_(float v) {
    float e = __expf(-v);
    return __fdividef(1.0f, 1.0f + e);
}
// Hardware tanh (1 MUFU). sigmoid(v) = 0.5 + 0.5*tanh(v/2)
__device__ __forceinline__ float ftanh_(float v) {
    float r;
    asm("tanh.approx.f32 %0, %1;" : "=f"(r) : "f"(v));
    return r;
}
// silu(v) = p + p*t, p = 0.5v
__device__ __forceinline__ float fsilu_(float v) {
    float p = 0.5f * v;
    float t = ftanh_(p);
    return fmaf(p, t, p);
}
// gate(h) = h^2*sigmoid(h) = q + q*t, q = 0.5h^2
__device__ __forceinline__ float fgate_(float h) {
    float t = ftanh_(0.5f * h);
    float q = 0.5f * h * h;
    return fmaf(q, t, q);
}

__device__ __forceinline__ void step2_(float2& h, const float2 xv,
                                       const float lam, const float2 bv) {
    h.x = fmaf(lam, h.x + fsilu_(xv.x), bv.x);
    h.y = fmaf(lam, h.y + fsilu_(xv.y), bv.y);
}
__device__ __forceinline__ float2 gate2_(const float2 h) {
    float2 g;
    g.x = fgate_(h.x);
    g.y = fgate_(h.y);
    return g;
}

__device__ __forceinline__ void cpasync8_(uint32_t s_dst, const void* g_src) {
    asm volatile("cp.async.ca.shared.global [%0], [%1], 8;"
                 :: "r"(s_dst), "l"(g_src));
}
__device__ __forceinline__ void cp_commit_() {
    asm volatile("cp.async.commit_group;");
}
__device__ __forceinline__ void cp_wait2_() {
    asm volatile("cp.async.wait_group 2;");
}
__device__ __forceinline__ void cp_wait0_() {
    asm volatile("cp.async.wait_group 0;");
}

// ---------------------------------------------------------------------------
// Warmup-truncated chunked recurrence, float2 lanes, cp.async smem pipeline.
//   h_t = lam * (silu(x_t) + h_{t-1}) + b
// Chunk starts from h=0 at t0-W with lam^W < 2^-12 (truncation ~2e-5 vs 1e-3
// tolerance; clamped -> exact fallback as lam->1; warmup reaching t=0 starts
// from h0 exactly). No inter-block communication.
// Main loop: 3-stage cp.async pipeline, 2 stages (64B/thread) in flight.
// Each thread copies/consumes only its own smem slots -> no __syncthreads.
// ---------------------------------------------------------------------------
__global__ __launch_bounds__(THR, 7) void e55_warm(
    const float2* __restrict__ x,
    const float2* __restrict__ h0,
    const float*  __restrict__ loglam,
    const float2* __restrict__ bias,
    float2* __restrict__ out,
    float2* __restrict__ hfinal)
{
    __shared__ float2 sx[NSTAGE][GSTEP][THR];

    const int bid = blockIdx.x;
    const int c   = bid >> 4;                 // chunk index [0, CC)
    const int lb  = bid & (NLB - 1);
    const int tid = threadIdx.x;
    const int j2  = lb * THR + tid;           // float2 lane [0, VLANES2)
    const int bi  = j2 >> 9;                  // batch
    const int dv  = j2 & (DV2 - 1);           // float2 column

    const float lam = fsig_exact_(loglam[0]);

    // Warmup depth: lam^W < 2^-12  =>  W = ceil(12*ln2 / -ln(lam))
    const int t0 = c * LL;
    int W;
    if (lam > 0.999f || lam <= 0.0f) {
        W = t0;                                // exact fallback
    } else {
        float wf = ceilf(__fdividef(8.3178f, -__logf(lam)));  // 12*ln2
        W = (wf >= (float)t0) ? t0 : (int)wf;
    }

    const float2 bv = bias[dv];
    float2 h = (t0 - W == 0) ? h0[j2] : make_float2(0.f, 0.f);

    const float2* xm = x + ((bi * TT + t0) * DV2 + dv);

    // ---- Kick off main-loop pipeline stages 0,1 BEFORE warmup compute ----
    uint32_t sbase = (uint32_t)__cvta_generic_to_shared(&sx[0][0][tid]);
    const uint32_t stage_bytes = GSTEP * THR * 8;
    const uint32_t step_bytes  = THR * 8;

    #pragma unroll
    for (int s = 0; s < NSTAGE - 1; s++) {
        #pragma unroll
        for (int k = 0; k < GSTEP; k++)
            cpasync8_(sbase + s * stage_bytes + k * step_bytes,
                      xm + (s * GSTEP + k) * DV2);
        cp_commit_();
    }

    // ---- Warmup: direct loads (L2-resident), recurrence only ----
    {
        const float2* xp = x + ((bi * TT + (t0 - W)) * DV2 + dv);
        int t = 0;
        #pragma unroll 1
        for (; t + 4 <= W; t += 4) {
            float2 xv[4];
            #pragma unroll
            for (int k = 0; k < 4; k++)
                xv[k] = xp[(t + k) * DV2];
            #pragma unroll
            for (int k = 0; k < 4; k++)
                step2_(h, xv[k], lam, bv);
        }
        #pragma unroll 1
        for (; t < W; t++)
            step2_(h, xp[t * DV2], lam, bv);
    }

    // ---- Main: software pipeline over NGROUP groups ----
    {
        float2* op = out + ((bi * TT + t0) * DV2 + dv);

        #pragma unroll 1
        for (int g = 0; g < NGROUP; g++) {
            // issue stage g+2 (empty commit keeps pending count constant)
            const int gi = g + NSTAGE - 1;
            if (gi < NGROUP) {
                const int s = gi % NSTAGE;
                #pragma unroll
                for (int k = 0; k < GSTEP; k++)
                    cpasync8_(sbase + s * stage_bytes + k * step_bytes,
                              xm + (gi * GSTEP + k) * DV2);
            }
            cp_commit_();
            cp_wait2_();             // group g now complete

            const int s = g % NSTAGE;
            #pragma unroll
            for (int k = 0; k < GSTEP; k++) {
                float2 xv = sx[s][k][tid];
                step2_(h, xv, lam, bv);
                __stcs(op + (g * GSTEP + k) * DV2, gate2_(h));
            }
        }
        cp_wait0_();                 // drain (empty tail groups)
    }

    if (c == CC - 1)
        hfinal[j2] = h;
}

// ---------------------------------------------------------------------------
// Launch
// Inputs: x [B,T,D] f32, h0 [B,D] f32, log_lambda [1] f32, b [D] f32
// Output: output [B,T,D] then h_final [B,D] (if space), f32
// ---------------------------------------------------------------------------
extern "C" void kernel_launch(void* const* d_in, const int* in_sizes, int n_in,
                              void* d_out, int out_size)
{
    const float2* x      = (const float2*)d_in[0];
    const float2* h0     = (const float2*)d_in[1];
    const float*  loglam = (const float*)d_in[2];
    const float2* bias   = (const float2*)d_in[3];
    float* out = (float*)d_out;

    const long n_output = (long)BB * TT * DD;

    float* hfinal;
    if ((long)out_size >= n_output + LANES) {
        hfinal = out + n_output;
    } else {
        void* p = nullptr;
        cudaGetSymbolAddress(&p, g_hfinal_scratch);
        hfinal = (float*)p;
    }

    e55_warm<<<CC * NLB, THR>>>(x, h0, loglam, bias,
                                (float2*)out, (float2*)hfinal);
}

// round 15
// speedup vs baseline: 1.0650x; 1.0650x over previous
#include <cuda_runtime.h>

// Problem constants
#define BB 8
#define TT 4096
#define DD 1024
#define DV2 (DD / 2)             // 512 float2 per row
#define LL 64                    // output timesteps per block
#define CC (TT / LL)             // 64 chunks
#define LANES (BB * DD)          // 8192 scalar lanes
#define VLANES2 (LANES / 2)      // 4096 float2 lanes
#define THR 256
#define NLB (VLANES2 / THR)      // 16 lane-blocks per chunk

__device__ float g_hfinal_scratch[LANES];

// Exact-ish sigmoid (used once, for lam)
__device__ __forceinline__ float fsig_exact_(float v) {
    float e = __expf(-v);
    return __fdividef(1.0f, 1.0f + e);
}
// Hardware tanh (1 MUFU). sigmoid(v) = 0.5 + 0.5*tanh(v/2)
__device__ __forceinline__ float ftanh_(float v) {
    float r;
    asm("tanh.approx.f32 %0, %1;" : "=f"(r) : "f"(v));
    return r;
}
// silu(v) = p + p*t, p = 0.5v
__device__ __forceinline__ float fsilu_(float v) {
    float p = 0.5f * v;
    float t = ftanh_(p);
    return fmaf(p, t, p);
}
// gate(h) = h^2*sigmoid(h) = q + q*t, q = 0.5h^2
__device__ __forceinline__ float fgate_(float h) {
    float t = ftanh_(0.5f * h);
    float q = 0.5f * h * h;
    return fmaf(q, t, q);
}

__device__ __forceinline__ void step2_(float2& h, const float2 xv,
                                       const float lam, const float2 bv) {
    h.x = fmaf(lam, h.x + fsilu_(xv.x), bv.x);
    h.y = fmaf(lam, h.y + fsilu_(xv.y), bv.y);
}
__device__ __forceinline__ float2 gate2_(const float2 h) {
    float2 g;
    g.x = fgate_(h.x);
    g.y = fgate_(h.y);
    return g;
}

// ---------------------------------------------------------------------------
// Warmup-truncated chunked recurrence, float2 lanes, burst stores.
//   h_t = lam * (silu(x_t) + h_{t-1}) + b
// Chunk starts from h=0 at t0-W with lam^W < 2^-11 (truncation error ~4e-5
// vs 1e-3 tolerance; clamped to t0 -> exact fallback as lam->1; warmup
// reaching t=0 starts from h0 exactly). No inter-block communication.
// 8192 warps (~55/SM, one balanced wave). Main loop groups each 4-batch as
// load*4 -> compute*4 -> store*4 so DRAM sees 4-deep read and write bursts
// instead of fine-grained read/write alternation (bus-turnaround relief).
// ---------------------------------------------------------------------------
__global__ __launch_bounds__(THR, 7) void e55_warm(
    const float2* __restrict__ x,
    const float2* __restrict__ h0,
    const float*  __restrict__ loglam,
    const float2* __restrict__ bias,
    float2* __restrict__ out,
    float2* __restrict__ hfinal)
{
    const int bid = blockIdx.x;
    const int c   = bid >> 4;                 // chunk index [0, CC)
    const int lb  = bid & (NLB - 1);
    const int j2  = lb * THR + threadIdx.x;   // float2 lane [0, VLANES2)
    const int bi  = j2 >> 9;                  // batch
    const int dv  = j2 & (DV2 - 1);           // float2 column

    const float lam = fsig_exact_(loglam[0]);

    // Warmup depth: lam^W < 2^-11  =>  W = ceil(11*ln2 / -ln(lam))
    const int t0 = c * LL;
    int W;
    if (lam > 0.999f || lam <= 0.0f) {
        W = t0;                                // exact fallback
    } else {
        float wf = ceilf(__fdividef(7.6246f, -__logf(lam)));  // 11*ln2
        W = (wf >= (float)t0) ? t0 : (int)wf;
    }

    const float2 bv = bias[dv];
    float2 h = (t0 - W == 0) ? h0[j2] : make_float2(0.f, 0.f);

    // ---- Warmup: recurrence only, no stores (default cache: L2 reuse) ----
    {
        const float2* xp = x + ((bi * TT + (t0 - W)) * DV2 + dv);
        int t = 0;
        #pragma unroll 1
        for (; t + 4 <= W; t += 4) {
            float2 xv[4];
            #pragma unroll
            for (int k = 0; k < 4; k++)
                xv[k] = xp[(t + k) * DV2];
            #pragma unroll
            for (int k = 0; k < 4; k++)
                step2_(h, xv[k], lam, bv);
        }
        #pragma unroll 1
        for (; t < W; t++)
            step2_(h, xp[t * DV2], lam, bv);
    }

    // ---- Main: load*4 -> compute*4 -> store*4 bursts ----
    {
        const float2* xm = x + ((bi * TT + t0) * DV2 + dv);
        float2*       op = out + ((bi * TT + t0) * DV2 + dv);

        #pragma unroll 1
        for (int tb = 0; tb < LL; tb += 4) {
            float2 xv[4];
            #pragma unroll
            for (int k = 0; k < 4; k++)
                xv[k] = xm[(tb + k) * DV2];

            float2 g[4];
            #pragma unroll
            for (int k = 0; k < 4; k++) {
                step2_(h, xv[k], lam, bv);
                g[k] = gate2_(h);
            }

            #pragma unroll
            for (int k = 0; k < 4; k++)
                __stcs(op + (tb + k) * DV2, g[k]);
        }
    }

    if (c == CC - 1)
        hfinal[j2] = h;
}

// ---------------------------------------------------------------------------
// Launch
// Inputs: x [B,T,D] f32, h0 [B,D] f32, log_lambda [1] f32, b [D] f32
// Output: output [B,T,D] then h_final [B,D] (if space), f32
// ---------------------------------------------------------------------------
extern "C" void kernel_launch(void* const* d_in, const int* in_sizes, int n_in,
                              void* d_out, int out_size)
{
    const float2* x      = (const float2*)d_in[0];
    const float2* h0     = (const float2*)d_in[1];
    const float*  loglam = (const float*)d_in[2];
    const float2* bias   = (const float2*)d_in[3];
    float* out = (float*)d_out;

    const long n_output = (long)BB * TT * DD;

    float* hfinal;
    if ((long)out_size >= n_output + LANES) {
        hfinal = out + n_output;
    } else {
        void* p = nullptr;
        cudaGetSymbolAddress(&p, g_hfinal_scratch);
        hfinal = (float*)p;
    }

    e55_warm<<<CC * NLB, THR>>>(x, h0, loglam, bias,
                                (float2*)out, (float2*)hfinal);
}

// round 16
// speedup vs baseline: 1.0732x; 1.0076x over previous
#include <cuda_runtime.h>

// Problem constants
#define BB 8
#define TT 4096
#define DD 1024
#define DV2 (DD / 2)             // 512 float2 per row
#define LL 64                    // output timesteps per block
#define CC (TT / LL)             // 64 chunks
#define LANES (BB * DD)          // 8192 scalar lanes
#define VLANES2 (LANES / 2)      // 4096 float2 lanes
#define THR 256
#define NLB (VLANES2 / THR)      // 16 lane-blocks per chunk

__device__ float g_hfinal_scratch[LANES];

// Exact-ish sigmoid (used once, for lam)
__device__ __forceinline__ float fsig_exact_(float v) {
    float e = __expf(-v);
    return __fdividef(1.0f, 1.0f + e);
}
// Hardware tanh (1 MUFU). sigmoid(v) = 0.5 + 0.5*tanh(v/2)
__device__ __forceinline__ float ftanh_(float v) {
    float r;
    asm("tanh.approx.f32 %0, %1;" : "=f"(r) : "f"(v));
    return r;
}
// silu(v) = p + p*t, p = 0.5v
__device__ __forceinline__ float fsilu_(float v) {
    float p = 0.5f * v;
    float t = ftanh_(p);
    return fmaf(p, t, p);
}
// gate(h) = h^2*sigmoid(h) = q + q*t, q = 0.5h^2
__device__ __forceinline__ float fgate_(float h) {
    float t = ftanh_(0.5f * h);
    float q = 0.5f * h * h;
    return fmaf(q, t, q);
}

__device__ __forceinline__ void step2_(float2& h, const float2 xv,
                                       const float lam, const float2 bv) {
    h.x = fmaf(lam, h.x + fsilu_(xv.x), bv.x);
    h.y = fmaf(lam, h.y + fsilu_(xv.y), bv.y);
}
__device__ __forceinline__ float2 gate2_(const float2 h) {
    float2 g;
    g.x = fgate_(h.x);
    g.y = fgate_(h.y);
    return g;
}

// ---------------------------------------------------------------------------
// Warmup-truncated chunked recurrence, float2 lanes, burst stores.
//   h_t = lam * (silu(x_t) + h_{t-1}) + b
// Chunk starts from h=0 at t0-W with lam^W < 2^-10 (truncation error ~6e-5
// vs 1e-3 tolerance; clamped to t0 -> exact fallback as lam->1; warmup
// reaching t=0 starts from h0 exactly). No inter-block communication.
// 8192 warps (~55/SM, one balanced wave). Main loop: load*4 -> compute*4 ->
// store*4 bursts (DRAM bus-turnaround relief vs fine-grained alternation).
// ---------------------------------------------------------------------------
__global__ __launch_bounds__(THR, 7) void e55_warm(
    const float2* __restrict__ x,
    const float2* __restrict__ h0,
    const float*  __restrict__ loglam,
    const float2* __restrict__ bias,
    float2* __restrict__ out,
    float2* __restrict__ hfinal)
{
    const int bid = blockIdx.x;
    const int c   = bid >> 4;                 // chunk index [0, CC)
    const int lb  = bid & (NLB - 1);
    const int j2  = lb * THR + threadIdx.x;   // float2 lane [0, VLANES2)
    const int bi  = j2 >> 9;                  // batch
    const int dv  = j2 & (DV2 - 1);           // float2 column

    const float lam = fsig_exact_(loglam[0]);

    // Warmup depth: lam^W < 2^-10  =>  W = ceil(10*ln2 / -ln(lam))
    const int t0 = c * LL;
    int W;
    if (lam > 0.999f || lam <= 0.0f) {
        W = t0;                                // exact fallback
    } else {
        float wf = ceilf(__fdividef(6.9315f, -__logf(lam)));  // 10*ln2
        W = (wf >= (float)t0) ? t0 : (int)wf;
    }

    const float2 bv = bias[dv];
    float2 h = (t0 - W == 0) ? h0[j2] : make_float2(0.f, 0.f);

    // ---- Warmup: recurrence only, no stores (default cache: L2 reuse) ----
    {
        const float2* xp = x + ((bi * TT + (t0 - W)) * DV2 + dv);
        int t = 0;
        #pragma unroll 1
        for (; t + 4 <= W; t += 4) {
            float2 xv[4];
            #pragma unroll
            for (int k = 0; k < 4; k++)
                xv[k] = xp[(t + k) * DV2];
            #pragma unroll
            for (int k = 0; k < 4; k++)
                step2_(h, xv[k], lam, bv);
        }
        #pragma unroll 1
        for (; t < W; t++)
            step2_(h, xp[t * DV2], lam, bv);
    }

    // ---- Main: load*4 -> compute*4 -> store*4 bursts ----
    {
        const float2* xm = x + ((bi * TT + t0) * DV2 + dv);
        float2*       op = out + ((bi * TT + t0) * DV2 + dv);

        #pragma unroll 1
        for (int tb = 0; tb < LL; tb += 4) {
            float2 xv[4];
            #pragma unroll
            for (int k = 0; k < 4; k++)
                xv[k] = xm[(tb + k) * DV2];

            float2 g[4];
            #pragma unroll
            for (int k = 0; k < 4; k++) {
                step2_(h, xv[k], lam, bv);
                g[k] = gate2_(h);
            }

            #pragma unroll
            for (int k = 0; k < 4; k++)
                __stcs(op + (tb + k) * DV2, g[k]);
        }
    }

    if (c == CC - 1)
        hfinal[j2] = h;
}

// ---------------------------------------------------------------------------
// Launch
// Inputs: x [B,T,D] f32, h0 [B,D] f32, log_lambda [1] f32, b [D] f32
// Output: output [B,T,D] then h_final [B,D] (if space), f32
// ---------------------------------------------------------------------------
extern "C" void kernel_launch(void* const* d_in, const int* in_sizes, int n_in,
                              void* d_out, int out_size)
{
    const float2* x      = (const float2*)d_in[0];
    const float2* h0     = (const float2*)d_in[1];
    const float*  loglam = (const float*)d_in[2];
    const float2* bias   = (const float2*)d_in[3];
    float* out = (float*)d_out;

    const long n_output = (long)BB * TT * DD;

    float* hfinal;
    if ((long)out_size >= n_output + LANES) {
        hfinal = out + n_output;
    } else {
        void* p = nullptr;
        cudaGetSymbolAddress(&p, g_hfinal_scratch);
        hfinal = (float*)p;
    }

    e55_warm<<<CC * NLB, THR>>>(x, h0, loglam, bias,
                                (float2*)out, (float2*)hfinal);
}

// round 17
// speedup vs baseline: 1.0870x; 1.0129x over previous
#include <cuda_runtime.h>

// Problem constants
#define BB 8
#define TT 4096
#define DD 1024
#define DV2 (DD / 2)             // 512 float2 per row
#define LL 64                    // output timesteps per block
#define CC (TT / LL)             // 64 chunks
#define LANES (BB * DD)          // 8192 scalar lanes
#define VLANES2 (LANES / 2)      // 4096 float2 lanes
#define THR 256
#define NLB (VLANES2 / THR)      // 16 lane-blocks per chunk

__device__ float g_hfinal_scratch[LANES];

// Exact-ish sigmoid (used once, for lam)
__device__ __forceinline__ float fsig_exact_(float v) {
    float e = __expf(-v);
    return __fdividef(1.0f, 1.0f + e);
}
// Hardware tanh (1 MUFU). sigmoid(v) = 0.5 + 0.5*tanh(v/2)
__device__ __forceinline__ float ftanh_(float v) {
    float r;
    asm("tanh.approx.f32 %0, %1;" : "=f"(r) : "f"(v));
    return r;
}
// silu(v) = p + p*t, p = 0.5v
__device__ __forceinline__ float fsilu_(float v) {
    float p = 0.5f * v;
    float t = ftanh_(p);
    return fmaf(p, t, p);
}
// gate(h) = h^2*sigmoid(h) = q + q*t, q = 0.5h^2
__device__ __forceinline__ float fgate_(float h) {
    float t = ftanh_(0.5f * h);
    float q = 0.5f * h * h;
    return fmaf(q, t, q);
}

__device__ __forceinline__ void step2_(float2& h, const float2 xv,
                                       const float lam, const float2 bv) {
    h.x = fmaf(lam, h.x + fsilu_(xv.x), bv.x);
    h.y = fmaf(lam, h.y + fsilu_(xv.y), bv.y);
}
__device__ __forceinline__ float2 gate2_(const float2 h) {
    float2 g;
    g.x = fgate_(h.x);
    g.y = fgate_(h.y);
    return g;
}

// ---------------------------------------------------------------------------
// Warmup-truncated chunked recurrence, float2 lanes, prefetched burst stores.
//   h_t = lam * (silu(x_t) + h_{t-1}) + b
// Chunk starts from h=0 at t0-W with lam^W < 2^-10 (truncation error ~6e-5
// vs 1e-3 tolerance; clamped to t0 -> exact fallback as lam->1; warmup
// reaching t=0 starts from h0 exactly). No inter-block communication.
// 8192 warps (~55/SM, one balanced wave). Main loop: loads for batch t+1
// are issued BEFORE batch t's compute+store burst, so reads stay outstanding
// through the store phase (read-pipe idle window of the plain burst form).
// ---------------------------------------------------------------------------
__global__ __launch_bounds__(THR, 7) void e55_warm(
    const float2* __restrict__ x,
    const float2* __restrict__ h0,
    const float*  __restrict__ loglam,
    const float2* __restrict__ bias,
    float2* __restrict__ out,
    float2* __restrict__ hfinal)
{
    const int bid = blockIdx.x;
    const int c   = bid >> 4;                 // chunk index [0, CC)
    const int lb  = bid & (NLB - 1);
    const int j2  = lb * THR + threadIdx.x;   // float2 lane [0, VLANES2)
    const int bi  = j2 >> 9;                  // batch
    const int dv  = j2 & (DV2 - 1);           // float2 column

    const float lam = fsig_exact_(loglam[0]);

    // Warmup depth: lam^W < 2^-10  =>  W = ceil(10*ln2 / -ln(lam))
    const int t0 = c * LL;
    int W;
    if (lam > 0.999f || lam <= 0.0f) {
        W = t0;                                // exact fallback
    } else {
        float wf = ceilf(__fdividef(6.9315f, -__logf(lam)));  // 10*ln2
        W = (wf >= (float)t0) ? t0 : (int)wf;
    }

    const float2 bv = bias[dv];
    float2 h = (t0 - W == 0) ? h0[j2] : make_float2(0.f, 0.f);

    // ---- Warmup: recurrence only, no stores (default cache: L2 reuse) ----
    {
        const float2* xp = x + ((bi * TT + (t0 - W)) * DV2 + dv);
        int t = 0;
        #pragma unroll 1
        for (; t + 4 <= W; t += 4) {
            float2 xv[4];
            #pragma unroll
            for (int k = 0; k < 4; k++)
                xv[k] = xp[(t + k) * DV2];
            #pragma unroll
            for (int k = 0; k < 4; k++)
                step2_(h, xv[k], lam, bv);
        }
        #pragma unroll 1
        for (; t < W; t++)
            step2_(h, xp[t * DV2], lam, bv);
    }

    // ---- Main: prefetch(t+1) -> compute(t) -> store-burst(t) ----
    {
        const float2* xm = x + ((bi * TT + t0) * DV2 + dv);
        float2*       op = out + ((bi * TT + t0) * DV2 + dv);

        float2 xv[4];
        #pragma unroll
        for (int k = 0; k < 4; k++)
            xv[k] = xm[k * DV2];

        #pragma unroll 1
        for (int tb = 0; tb < LL; tb += 4) {
            // prefetch next batch before this batch's compute+stores
            const int tn = (tb + 4 < LL) ? (tb + 4) : tb;
            float2 xn[4];
            #pragma unroll
            for (int k = 0; k < 4; k++)
                xn[k] = xm[(tn + k) * DV2];

            float2 g[4];
            #pragma unroll
            for (int k = 0; k < 4; k++) {
                step2_(h, xv[k], lam, bv);
                g[k] = gate2_(h);
            }

            #pragma unroll
            for (int k = 0; k < 4; k++)
                __stcs(op + (tb + k) * DV2, g[k]);

            #pragma unroll
            for (int k = 0; k < 4; k++)
                xv[k] = xn[k];
        }
    }

    if (c == CC - 1)
        hfinal[j2] = h;
}

// ---------------------------------------------------------------------------
// Launch
// Inputs: x [B,T,D] f32, h0 [B,D] f32, log_lambda [1] f32, b [D] f32
// Output: output [B,T,D] then h_final [B,D] (if space), f32
// ---------------------------------------------------------------------------
extern "C" void kernel_launch(void* const* d_in, const int* in_sizes, int n_in,
                              void* d_out, int out_size)
{
    const float2* x      = (const float2*)d_in[0];
    const float2* h0     = (const float2*)d_in[1];
    const float*  loglam = (const float*)d_in[2];
    const float2* bias   = (const float2*)d_in[3];
    float* out = (float*)d_out;

    const long n_output = (long)BB * TT * DD;

    float* hfinal;
    if ((long)out_size >= n_output + LANES) {
        hfinal = out + n_output;
    } else {
        void* p = nullptr;
        cudaGetSymbolAddress(&p, g_hfinal_scratch);
        hfinal = (float*)p;
    }

    e55_warm<<<CC * NLB, THR>>>(x, h0, loglam, bias,
                                (float2*)out, (float2*)hfinal);
}